// round 16
// baseline (speedup 1.0000x reference)
#include <cuda_runtime.h>
#include <cuda_fp16.h>
#include <stdint.h>

// ---------------------------------------------------------------------------
// Problem constants
// ---------------------------------------------------------------------------
#define B_  8
#define T_  2048
#define C_  512
#define U_  512
#define NG  1536          // 3*U
#define KP  1024          // 2*C (W=2 window)
#define MM  (B_ * T_)     // 16384
#define NITER 16          // KP / BK, single fp16 pass

// GEMM tiling: CTA 128x128, warp 32x64 (8 warps: 4 along M x 2 along N)
#define BM 128
#define BN 128
#define BK 64             // fp16 per chunk (128B data/row)
#define LDR 144           // padded smem row bytes (128 data + 16 pad)
#define A_STAGE (BM * LDR)                 // 18432
#define B_STAGE (BN * LDR)                 // 18432
#define STAGE_BYTES (A_STAGE + B_STAGE)    // 36864
#define DEPTH 3
#define SMEM_REQ (DEPTH * STAGE_BYTES)     // 110592 -> 2 CTAs/SM

// scan chunking (single-pass decoupled lookback)
#define NCH 64
#define CL  (T_ / NCH)    // 32

// prep grid split: x-part blocks, W-part blocks, then 1 flag-clear block
#define XWORK (MM * C_ / 4)                // 2097152 float4s
#define XF4_PER_THREAD 4
#define NXBLK (XWORK / (256 * XF4_PER_THREAD))   // 2048 blocks
#define NWBLK ((NG / 32) * (KP / 32))            // 1536 blocks

// ---------------------------------------------------------------------------
// Device scratch (static, no runtime alloc). Gates stored as fp16.
// ---------------------------------------------------------------------------
__device__ __half g_Zh[(size_t)MM * U_];
__device__ __half g_Fh[(size_t)MM * U_];
__device__ __half g_Oh[(size_t)MM * U_];
__device__ __half g_X16[(size_t)MM * C_];
__device__ __half g_WT[(size_t)NG * KP];
__device__ float g_aP[B_ * NCH * U_];
__device__ float g_aH[B_ * NCH * U_];
__device__ int   g_flag[B_ * NCH];

// ---------------------------------------------------------------------------
// Helpers
// ---------------------------------------------------------------------------
__device__ __forceinline__ uint32_t smem_u32(const void* p) {
    uint32_t a;
    asm("{ .reg .u64 t; cvta.to.shared.u64 t, %1; cvt.u32.u64 %0, t; }"
        : "=r"(a) : "l"(p));
    return a;
}

#define CP16P(saddr, gptr, sz) \
    asm volatile("cp.async.cg.shared.global [%0], [%1], 16, %2;" \
                 :: "r"(saddr), "l"(gptr), "r"(sz))
#define CP_COMMIT() asm volatile("cp.async.commit_group;")
#define CP_WAIT1()  asm volatile("cp.async.wait_group 1;")

#define LDSM_X4(r0, r1, r2, r3, addr) \
    asm volatile("ldmatrix.sync.aligned.m8n8.x4.shared.b16 {%0,%1,%2,%3}, [%4];" \
                 : "=r"(r0), "=r"(r1), "=r"(r2), "=r"(r3) : "r"(addr))

#define MMA16816(d, a, b0, b1) \
    asm volatile("mma.sync.aligned.m16n8k16.row.col.f32.f16.f16.f32 " \
                 "{%0,%1,%2,%3}, {%4,%5,%6,%7}, {%8,%9}, {%0,%1,%2,%3};" \
                 : "+f"((d)[0]), "+f"((d)[1]), "+f"((d)[2]), "+f"((d)[3]) \
                 : "r"((a)[0]), "r"((a)[1]), "r"((a)[2]), "r"((a)[3]), \
                   "r"(b0), "r"(b1))

__device__ __forceinline__ float tanh_fast(float x) {
    float r; asm("tanh.approx.f32 %0, %1;" : "=f"(r) : "f"(x)); return r;
}
__device__ __forceinline__ float sig_fast(float x) {
    float e; asm("ex2.approx.f32 %0, %1;" : "=f"(e) : "f"(-x * 1.4426950408889634f));
    float r; asm("rcp.approx.f32 %0, %1;" : "=f"(r) : "f"(1.0f + e)); return r;
}

// ---------------------------------------------------------------------------
// prep_all: blocks [0,NXBLK): fp32 x -> fp16 (4 float4 per thread);
//           blocks [NXBLK, NXBLK+NWBLK): transpose W tile -> fp16 WT;
//           last block: zero lookback flags (ordered before scan by launch seq)
// ---------------------------------------------------------------------------
__global__ __launch_bounds__(256) void prep_all(const float* __restrict__ x,
                                                const float* __restrict__ kern) {
    __shared__ __half sh[32][33];
    const int blk = blockIdx.x;
    if (blk < NXBLK) {
        size_t g0 = (size_t)blk * (256 * XF4_PER_THREAD) + threadIdx.x;
        float4 v[XF4_PER_THREAD];
#pragma unroll
        for (int i = 0; i < XF4_PER_THREAD; i++)
            v[i] = ((const float4*)x)[g0 + (size_t)i * 256];
#pragma unroll
        for (int i = 0; i < XF4_PER_THREAD; i++) {
            __half2 a; a.x = __float2half(v[i].x); a.y = __float2half(v[i].y);
            __half2 b; b.x = __float2half(v[i].z); b.y = __float2half(v[i].w);
            size_t g = g0 + (size_t)i * 256;
            ((__half2*)g_X16)[g * 2]     = a;
            ((__half2*)g_X16)[g * 2 + 1] = b;
        }
    } else if (blk < NXBLK + NWBLK) {
        const int wb = blk - NXBLK;          // 0..NWBLK-1
        const int bx = wb % (NG / 32);       // n-tile
        const int by = wb / (NG / 32);       // k-tile
        const int tx = threadIdx.x & 31;
        const int ty0 = threadIdx.x >> 5;    // 0..7
#pragma unroll
        for (int i = 0; i < 4; i++) {
            int ty = ty0 + i * 8;
            sh[ty][tx] = __float2half(kern[(size_t)(by * 32 + ty) * NG + bx * 32 + tx]);
        }
        __syncthreads();
#pragma unroll
        for (int i = 0; i < 4; i++) {
            int ty = ty0 + i * 8;
            g_WT[(size_t)(bx * 32 + ty) * KP + by * 32 + tx] = sh[tx][ty];
        }
    } else {
        // zero lookback flags for this run
        int i = threadIdx.x;
        if (i < B_ * NCH) g_flag[i] = 0;
    }
}

// ---------------------------------------------------------------------------
// GEMM: gates[16384,1536] = A16[16384,1024] @ WT^T, single fp16 pass.
// A row m, k: source X16[m + w - 1, c]  (w=k/512, c=k%512),
// zero row when (w==0 && m%2048==0). Fused bias + activation epilogue,
// gates stored fp16. CTA 128x128, BK=64, 2 CTAs/SM.
// ---------------------------------------------------------------------------
__global__ __launch_bounds__(256, 2) void mma_gates(const float* __restrict__ bias) {
    extern __shared__ char smem[];
    const uint32_t sbase = smem_u32(smem);

    const int tid = threadIdx.x;
    const int wid = tid >> 5;
    const int lane = tid & 31;
    const int n0 = blockIdx.x * BN;
    const int m0 = blockIdx.y * BM;

    const int wm = (wid & 3) * 32;      // warp m offset (4 warps along M)
    const int wn = (wid >> 2) * 64;     // warp n offset (2 warps along N)

    // cp.async: 2048 16B-chunks per stage / 256 threads = 8 per thread
    const int rowq = tid >> 3;          // 0..31
    const int jq   = tid & 7;           // chunk-in-row (8 per 128B row)

#define LOAD_STAGE(cc) do { \
    const int _c = (cc); \
    const int _kb = _c * BK; \
    const uint32_t _st = sbase + (uint32_t)(_c % DEPTH) * STAGE_BYTES; \
    const int _k = _kb + jq * 8; \
    const int _w = _k >> 9; \
    const int _cc2 = _k & 511; \
    _Pragma("unroll") \
    for (int _i = 0; _i < 4; _i++) { \
        int _row = rowq + _i * 32; \
        int _m = m0 + _row; \
        int _r = _m + _w - 1; \
        uint32_t _sz = (_w == 0 && (_m & (T_ - 1)) == 0) ? 0u : 16u; \
        if (_sz == 0u) _r = _m; \
        const void* _gp = g_X16 + (size_t)_r * C_ + _cc2; \
        CP16P(_st + (uint32_t)(_row * LDR + jq * 16), _gp, _sz); \
    } \
    _Pragma("unroll") \
    for (int _i = 0; _i < 4; _i++) { \
        int _row = rowq + _i * 32; \
        const void* _gp = g_WT + (size_t)(n0 + _row) * KP + _kb + jq * 8; \
        CP16P(_st + (uint32_t)(A_STAGE + _row * LDR + jq * 16), _gp, 16u); \
    } \
    CP_COMMIT(); \
} while (0)

    float acc[2][8][4];
#pragma unroll
    for (int mt = 0; mt < 2; mt++)
#pragma unroll
        for (int nt = 0; nt < 8; nt++)
#pragma unroll
            for (int r = 0; r < 4; r++) acc[mt][nt][r] = 0.0f;

    LOAD_STAGE(0);
    LOAD_STAGE(1);

    // ldmatrix lane address components (fixed per thread)
    const int a_row = lane & 15;             // row within m16 tile
    const int a_chk = lane >> 4;             // 0/1 -> k-half
    const int b_row = (lane & 7) + ((lane >> 4) << 3);  // n row within pair
    const int b_chk = (lane >> 3) & 1;       // k-half select

#pragma unroll 1
    for (int cc = 0; cc < NITER; cc++) {
        CP_WAIT1();
        __syncthreads();
        if (cc + 2 < NITER) {
            LOAD_STAGE(cc + 2);
        } else {
            CP_COMMIT();
        }

        const uint32_t st = sbase + (uint32_t)(cc % DEPTH) * STAGE_BYTES;
        const uint32_t sA = st + (uint32_t)((wm + a_row) * LDR);
        const uint32_t sB = st + (uint32_t)(A_STAGE + (wn + b_row) * LDR);

#pragma unroll
        for (int ks = 0; ks < 4; ks++) {
            uint32_t a[2][4];
            uint32_t b[4][4];
#pragma unroll
            for (int mt = 0; mt < 2; mt++) {
                uint32_t ad = sA + (uint32_t)(mt * 16 * LDR + (a_chk + ks * 2) * 16);
                LDSM_X4(a[mt][0], a[mt][1], a[mt][2], a[mt][3], ad);
            }
#pragma unroll
            for (int p = 0; p < 4; p++) {
                uint32_t bd = sB + (uint32_t)(p * 16 * LDR + (b_chk + ks * 2) * 16);
                LDSM_X4(b[p][0], b[p][1], b[p][2], b[p][3], bd);
            }
#pragma unroll
            for (int mt = 0; mt < 2; mt++)
#pragma unroll
                for (int p = 0; p < 4; p++) {
                    MMA16816(acc[mt][2 * p],     a[mt], b[p][0], b[p][1]);
                    MMA16816(acc[mt][2 * p + 1], a[mt], b[p][2], b[p][3]);
                }
        }
    }

    // ---- epilogue: bias + activation + fp16 store, straight from registers --
    const int ng = n0 + wn;                   // warp n base (global)
    const int gate = ng >> 9;                 // 0:z 1:f 2:o
    __half* dst = (gate == 0) ? g_Zh : ((gate == 1) ? g_Fh : g_Oh);
    const int colw = (ng & 511) + (lane & 3) * 2;

    float bs0[8], bs1[8];
#pragma unroll
    for (int nt = 0; nt < 8; nt++) {
        bs0[nt] = __ldg(bias + ng + (lane & 3) * 2 + nt * 8);
        bs1[nt] = __ldg(bias + ng + (lane & 3) * 2 + nt * 8 + 1);
    }

#pragma unroll
    for (int mt = 0; mt < 2; mt++) {
        int row = m0 + wm + mt * 16 + (lane >> 2);
        __half* p0 = dst + (size_t)row * U_;
        __half* p1 = dst + (size_t)(row + 8) * U_;
#pragma unroll
        for (int nt = 0; nt < 8; nt++) {
            int col = colw + nt * 8;
            float g0 = acc[mt][nt][0] + bs0[nt];
            float g1 = acc[mt][nt][1] + bs1[nt];
            float g2 = acc[mt][nt][2] + bs0[nt];
            float g3 = acc[mt][nt][3] + bs1[nt];
            __half2 v0, v1;
            if (gate == 0) {
                v0.x = __float2half(tanh_fast(g0)); v0.y = __float2half(tanh_fast(g1));
                v1.x = __float2half(tanh_fast(g2)); v1.y = __float2half(tanh_fast(g3));
            } else {
                v0.x = __float2half(sig_fast(g0)); v0.y = __float2half(sig_fast(g1));
                v1.x = __float2half(sig_fast(g2)); v1.y = __float2half(sig_fast(g3));
            }
            *(__half2*)(p0 + col) = v0;
            *(__half2*)(p1 + col) = v1;
        }
    }
}

// ---------------------------------------------------------------------------
// Single-pass fo-pool scan with decoupled lookback.
// CTA = (b, ch): 512 threads, one u each. Local scan keeps f,z in registers;
// publish chunk affine (P,H); lookback over lower chunks of same b (strictly
// lower blockIdx -> dispatched earlier -> no deadlock); replay from regs.
// Combine order identical to the 3-pass version -> bit-identical result.
// ---------------------------------------------------------------------------
__global__ __launch_bounds__(512) void scan_one(const float* __restrict__ init,
                                                float* __restrict__ out) {
    const int bid = blockIdx.x;          // b*NCH + ch (ch fast)
    const int b  = bid >> 6;
    const int ch = bid & (NCH - 1);
    const int u  = threadIdx.x;
    const size_t base = ((size_t)b * T_ + (size_t)ch * CL) * U_ + u;

    // ---- local scan; f,z stay in registers ----
    float f[CL], z[CL];
    float h = 0.0f, P = 1.0f;
#pragma unroll
    for (int t = 0; t < CL; t++) {
        f[t] = __half2float(g_Fh[base + (size_t)t * U_]);
        z[t] = __half2float(g_Zh[base + (size_t)t * U_]);
        h = fmaf(f[t], h - z[t], z[t]);
        P *= f[t];
    }

    // ---- publish chunk aggregate ----
    const int agg = bid * U_ + u;
    g_aP[agg] = P;
    g_aH[agg] = h;
    __threadfence();
    __syncthreads();
    if (threadIdx.x == 0) atomicExch(&g_flag[bid], 1);

    // ---- lookback: wait for all predecessor chunks of this batch ----
    float hin = init[u];
    if (ch > 0) {
        if ((int)threadIdx.x < ch) {
            while (atomicAdd(&g_flag[(b << 6) + threadIdx.x], 0) == 0) { }
        }
        __syncthreads();
        __threadfence();
        const int ab = (b << 6) * U_ + u;
#pragma unroll 8
        for (int c = 0; c < ch; c++) {
            float Pc = g_aP[ab + c * U_];
            float Hc = g_aH[ab + c * U_];
            hin = fmaf(Pc, hin, Hc);
        }
    }

    // ---- replay from registers, apply output gate, streaming store ----
    float h2 = hin;
#pragma unroll
    for (int t = 0; t < CL; t++) {
        float o = __half2float(g_Oh[base + (size_t)t * U_]);
        h2 = fmaf(f[t], h2 - z[t], z[t]);
        __stcs(out + base + (size_t)t * U_, h2 * o);
    }
}

// ---------------------------------------------------------------------------
extern "C" void kernel_launch(void* const* d_in, const int* in_sizes, int n_in,
                              void* d_out, int out_size)
{
    const float* x    = (const float*)d_in[0];  // [8,2048,512]
    const float* kern = (const float*)d_in[1];  // [2,512,1536]
    const float* bias = (const float*)d_in[2];  // [1536]
    const float* init = (const float*)d_in[3];  // [1,512]
    float* out = (float*)d_out;                 // [8,2048,512]

    cudaFuncSetAttribute(mma_gates, cudaFuncAttributeMaxDynamicSharedMemorySize, SMEM_REQ);

    prep_all<<<NXBLK + NWBLK + 1, 256>>>(x, kern);
    mma_gates<<<dim3(NG / BN, MM / BM), 256, SMEM_REQ>>>(bias);
    scan_one<<<B_ * NCH, 512>>>(init, out);
}

// round 17
// speedup vs baseline: 1.1646x; 1.1646x over previous
#include <cuda_runtime.h>
#include <cuda_fp16.h>
#include <stdint.h>

// ---------------------------------------------------------------------------
// Problem constants
// ---------------------------------------------------------------------------
#define B_  8
#define T_  2048
#define C_  512
#define U_  512
#define NG  1536          // 3*U
#define KP  1024          // 2*C (W=2 window)
#define MM  (B_ * T_)     // 16384
#define NITER 16          // KP / BK, single fp16 pass

// GEMM tiling: CTA 128x128, warp 32x64 (8 warps: 4 along M x 2 along N)
#define BM 128
#define BN 128
#define BK 64             // fp16 per chunk (128B data/row)
#define LDR 144           // padded smem row bytes (128 data + 16 pad)
#define A_STAGE (BM * LDR)                 // 18432
#define B_STAGE (BN * LDR)                 // 18432
#define STAGE_BYTES (A_STAGE + B_STAGE)    // 36864
#define DEPTH 3
#define SMEM_REQ (DEPTH * STAGE_BYTES)     // 110592 -> 2 CTAs/SM

// scan chunking
#define NCH 64
#define CL  (T_ / NCH)    // 32

// prep grid split: x-part blocks, then W-part blocks
#define XWORK (MM * C_ / 4)                // 2097152 float4s
#define XF4_PER_THREAD 4
#define NXBLK (XWORK / (256 * XF4_PER_THREAD))   // 2048 blocks
#define NWBLK ((NG / 32) * (KP / 32))            // 1536 blocks

// ---------------------------------------------------------------------------
// Device scratch (static, no runtime alloc). Gates stored as fp16.
// ---------------------------------------------------------------------------
__device__ __half g_Zh[(size_t)MM * U_];
__device__ __half g_Fh[(size_t)MM * U_];
__device__ __half g_Oh[(size_t)MM * U_];
__device__ __half g_X16[(size_t)MM * C_];
__device__ __half g_WT[(size_t)NG * KP];
__device__ float g_cH[B_ * NCH * U_];
__device__ float g_cP[B_ * NCH * U_];

// ---------------------------------------------------------------------------
// Helpers
// ---------------------------------------------------------------------------
__device__ __forceinline__ uint32_t smem_u32(const void* p) {
    uint32_t a;
    asm("{ .reg .u64 t; cvta.to.shared.u64 t, %1; cvt.u32.u64 %0, t; }"
        : "=r"(a) : "l"(p));
    return a;
}

#define CP16P(saddr, gptr, sz) \
    asm volatile("cp.async.cg.shared.global [%0], [%1], 16, %2;" \
                 :: "r"(saddr), "l"(gptr), "r"(sz))
#define CP_COMMIT() asm volatile("cp.async.commit_group;")
#define CP_WAIT1()  asm volatile("cp.async.wait_group 1;")

#define LDSM_X4(r0, r1, r2, r3, addr) \
    asm volatile("ldmatrix.sync.aligned.m8n8.x4.shared.b16 {%0,%1,%2,%3}, [%4];" \
                 : "=r"(r0), "=r"(r1), "=r"(r2), "=r"(r3) : "r"(addr))

#define MMA16816(d, a, b0, b1) \
    asm volatile("mma.sync.aligned.m16n8k16.row.col.f32.f16.f16.f32 " \
                 "{%0,%1,%2,%3}, {%4,%5,%6,%7}, {%8,%9}, {%0,%1,%2,%3};" \
                 : "+f"((d)[0]), "+f"((d)[1]), "+f"((d)[2]), "+f"((d)[3]) \
                 : "r"((a)[0]), "r"((a)[1]), "r"((a)[2]), "r"((a)[3]), \
                   "r"(b0), "r"(b1))

__device__ __forceinline__ float tanh_fast(float x) {
    float r; asm("tanh.approx.f32 %0, %1;" : "=f"(r) : "f"(x)); return r;
}
__device__ __forceinline__ float sig_fast(float x) {
    float e; asm("ex2.approx.f32 %0, %1;" : "=f"(e) : "f"(-x * 1.4426950408889634f));
    float r; asm("rcp.approx.f32 %0, %1;" : "=f"(r) : "f"(1.0f + e)); return r;
}

// ---------------------------------------------------------------------------
// prep_all: blocks [0,NXBLK): fp32 x -> fp16 (4 float4 per thread);
//           blocks [NXBLK, NXBLK+NWBLK): transpose W tile -> fp16 WT
// ---------------------------------------------------------------------------
__global__ __launch_bounds__(256) void prep_all(const float* __restrict__ x,
                                                const float* __restrict__ kern) {
    __shared__ __half sh[32][33];
    const int blk = blockIdx.x;
    if (blk < NXBLK) {
        size_t g0 = (size_t)blk * (256 * XF4_PER_THREAD) + threadIdx.x;
        float4 v[XF4_PER_THREAD];
#pragma unroll
        for (int i = 0; i < XF4_PER_THREAD; i++)
            v[i] = ((const float4*)x)[g0 + (size_t)i * 256];
#pragma unroll
        for (int i = 0; i < XF4_PER_THREAD; i++) {
            __half2 a; a.x = __float2half(v[i].x); a.y = __float2half(v[i].y);
            __half2 b; b.x = __float2half(v[i].z); b.y = __float2half(v[i].w);
            size_t g = g0 + (size_t)i * 256;
            ((__half2*)g_X16)[g * 2]     = a;
            ((__half2*)g_X16)[g * 2 + 1] = b;
        }
    } else {
        const int wb = blk - NXBLK;          // 0..NWBLK-1
        const int bx = wb % (NG / 32);       // n-tile
        const int by = wb / (NG / 32);       // k-tile
        const int tx = threadIdx.x & 31;
        const int ty0 = threadIdx.x >> 5;    // 0..7
#pragma unroll
        for (int i = 0; i < 4; i++) {
            int ty = ty0 + i * 8;
            sh[ty][tx] = __float2half(kern[(size_t)(by * 32 + ty) * NG + bx * 32 + tx]);
        }
        __syncthreads();
#pragma unroll
        for (int i = 0; i < 4; i++) {
            int ty = ty0 + i * 8;
            g_WT[(size_t)(bx * 32 + ty) * KP + by * 32 + tx] = sh[tx][ty];
        }
    }
}

// ---------------------------------------------------------------------------
// GEMM: gates[16384,1536] = A16[16384,1024] @ WT^T, single fp16 pass.
// A row m, k: source X16[m + w - 1, c]  (w=k/512, c=k%512),
// zero row when (w==0 && m%2048==0). Fused bias + activation epilogue,
// gates stored fp16. CTA 128x128, BK=64, 2 CTAs/SM.
// ---------------------------------------------------------------------------
__global__ __launch_bounds__(256, 2) void mma_gates(const float* __restrict__ bias) {
    extern __shared__ char smem[];
    const uint32_t sbase = smem_u32(smem);

    const int tid = threadIdx.x;
    const int wid = tid >> 5;
    const int lane = tid & 31;
    const int n0 = blockIdx.x * BN;
    const int m0 = blockIdx.y * BM;

    const int wm = (wid & 3) * 32;      // warp m offset (4 warps along M)
    const int wn = (wid >> 2) * 64;     // warp n offset (2 warps along N)

    // cp.async: 2048 16B-chunks per stage / 256 threads = 8 per thread
    const int rowq = tid >> 3;          // 0..31
    const int jq   = tid & 7;           // chunk-in-row (8 per 128B row)

#define LOAD_STAGE(cc) do { \
    const int _c = (cc); \
    const int _kb = _c * BK; \
    const uint32_t _st = sbase + (uint32_t)(_c % DEPTH) * STAGE_BYTES; \
    const int _k = _kb + jq * 8; \
    const int _w = _k >> 9; \
    const int _cc2 = _k & 511; \
    _Pragma("unroll") \
    for (int _i = 0; _i < 4; _i++) { \
        int _row = rowq + _i * 32; \
        int _m = m0 + _row; \
        int _r = _m + _w - 1; \
        uint32_t _sz = (_w == 0 && (_m & (T_ - 1)) == 0) ? 0u : 16u; \
        if (_sz == 0u) _r = _m; \
        const void* _gp = g_X16 + (size_t)_r * C_ + _cc2; \
        CP16P(_st + (uint32_t)(_row * LDR + jq * 16), _gp, _sz); \
    } \
    _Pragma("unroll") \
    for (int _i = 0; _i < 4; _i++) { \
        int _row = rowq + _i * 32; \
        const void* _gp = g_WT + (size_t)(n0 + _row) * KP + _kb + jq * 8; \
        CP16P(_st + (uint32_t)(A_STAGE + _row * LDR + jq * 16), _gp, 16u); \
    } \
    CP_COMMIT(); \
} while (0)

    float acc[2][8][4];
#pragma unroll
    for (int mt = 0; mt < 2; mt++)
#pragma unroll
        for (int nt = 0; nt < 8; nt++)
#pragma unroll
            for (int r = 0; r < 4; r++) acc[mt][nt][r] = 0.0f;

    LOAD_STAGE(0);
    LOAD_STAGE(1);

    // ldmatrix lane address components (fixed per thread)
    const int a_row = lane & 15;             // row within m16 tile
    const int a_chk = lane >> 4;             // 0/1 -> k-half
    const int b_row = (lane & 7) + ((lane >> 4) << 3);  // n row within pair
    const int b_chk = (lane >> 3) & 1;       // k-half select

#pragma unroll 1
    for (int cc = 0; cc < NITER; cc++) {
        CP_WAIT1();
        __syncthreads();
        if (cc + 2 < NITER) {
            LOAD_STAGE(cc + 2);
        } else {
            CP_COMMIT();
        }

        const uint32_t st = sbase + (uint32_t)(cc % DEPTH) * STAGE_BYTES;
        const uint32_t sA = st + (uint32_t)((wm + a_row) * LDR);
        const uint32_t sB = st + (uint32_t)(A_STAGE + (wn + b_row) * LDR);

#pragma unroll
        for (int ks = 0; ks < 4; ks++) {
            uint32_t a[2][4];
            uint32_t b[4][4];
#pragma unroll
            for (int mt = 0; mt < 2; mt++) {
                uint32_t ad = sA + (uint32_t)(mt * 16 * LDR + (a_chk + ks * 2) * 16);
                LDSM_X4(a[mt][0], a[mt][1], a[mt][2], a[mt][3], ad);
            }
#pragma unroll
            for (int p = 0; p < 4; p++) {
                uint32_t bd = sB + (uint32_t)(p * 16 * LDR + (b_chk + ks * 2) * 16);
                LDSM_X4(b[p][0], b[p][1], b[p][2], b[p][3], bd);
            }
#pragma unroll
            for (int mt = 0; mt < 2; mt++)
#pragma unroll
                for (int p = 0; p < 4; p++) {
                    MMA16816(acc[mt][2 * p],     a[mt], b[p][0], b[p][1]);
                    MMA16816(acc[mt][2 * p + 1], a[mt], b[p][2], b[p][3]);
                }
        }
    }

    // ---- epilogue: bias + activation + fp16 store, straight from registers --
    const int ng = n0 + wn;                   // warp n base (global)
    const int gate = ng >> 9;                 // 0:z 1:f 2:o
    __half* dst = (gate == 0) ? g_Zh : ((gate == 1) ? g_Fh : g_Oh);
    const int colw = (ng & 511) + (lane & 3) * 2;

    float bs0[8], bs1[8];
#pragma unroll
    for (int nt = 0; nt < 8; nt++) {
        bs0[nt] = __ldg(bias + ng + (lane & 3) * 2 + nt * 8);
        bs1[nt] = __ldg(bias + ng + (lane & 3) * 2 + nt * 8 + 1);
    }

#pragma unroll
    for (int mt = 0; mt < 2; mt++) {
        int row = m0 + wm + mt * 16 + (lane >> 2);
        __half* p0 = dst + (size_t)row * U_;
        __half* p1 = dst + (size_t)(row + 8) * U_;
#pragma unroll
        for (int nt = 0; nt < 8; nt++) {
            int col = colw + nt * 8;
            float g0 = acc[mt][nt][0] + bs0[nt];
            float g1 = acc[mt][nt][1] + bs1[nt];
            float g2 = acc[mt][nt][2] + bs0[nt];
            float g3 = acc[mt][nt][3] + bs1[nt];
            __half2 v0, v1;
            if (gate == 0) {
                v0.x = __float2half(tanh_fast(g0)); v0.y = __float2half(tanh_fast(g1));
                v1.x = __float2half(tanh_fast(g2)); v1.y = __float2half(tanh_fast(g3));
            } else {
                v0.x = __float2half(sig_fast(g0)); v0.y = __float2half(sig_fast(g1));
                v1.x = __float2half(sig_fast(g2)); v1.y = __float2half(sig_fast(g3));
            }
            *(__half2*)(p0 + col) = v0;
            *(__half2*)(p1 + col) = v1;
        }
    }
}

// ---------------------------------------------------------------------------
// Chunked fo-pool scan — pass1 builds per-chunk affine (P, H)
// ---------------------------------------------------------------------------
__global__ __launch_bounds__(256) void scan_pass1() {
    int id = blockIdx.x * 256 + threadIdx.x;       // B*NCH*U = 262144
    int u = id & 511;
    int ch = (id >> 9) & (NCH - 1);
    int b = id >> 15;
    size_t base = ((size_t)b * T_ + (size_t)ch * CL) * U_ + u;
    float h = 0.0f, P = 1.0f;
#pragma unroll 8
    for (int t = 0; t < CL; t++) {
        float f = __half2float(g_Fh[base + (size_t)t * U_]);
        float z = __half2float(g_Zh[base + (size_t)t * U_]);
        h = fmaf(f, h - z, z);
        P *= f;
    }
    int o = (b * NCH + ch) * U_ + u;
    g_cH[o] = h;
    g_cP[o] = P;
}

// ---------------------------------------------------------------------------
// pass23: each thread combines its chunk's predecessors (former pass2 work,
// data guaranteed complete by the kernel boundary), then replays its chunk.
// Combine order identical to the sequential pass2 -> bit-identical result.
// All threads in a block share ch -> uniform loop, coalesced L2-hot loads.
// ---------------------------------------------------------------------------
__global__ __launch_bounds__(256) void scan_pass23(const float* __restrict__ init,
                                                   float* __restrict__ out) {
    int id = blockIdx.x * 256 + threadIdx.x;       // 262144
    int u = id & 511;
    int ch = (id >> 9) & (NCH - 1);
    int b = id >> 15;

    // ---- combine predecessor aggregates into h_in ----
    float h = init[u];
    const int ab = b * NCH * U_ + u;
#pragma unroll 8
    for (int c = 0; c < ch; c++) {
        float Pc = g_cP[ab + c * U_];
        float Hc = g_cH[ab + c * U_];
        h = fmaf(Pc, h, Hc);
    }

    // ---- replay chunk, apply output gate ----
    size_t base = ((size_t)b * T_ + (size_t)ch * CL) * U_ + u;
#pragma unroll 8
    for (int t = 0; t < CL; t++) {
        size_t idx = base + (size_t)t * U_;
        float f = __half2float(g_Fh[idx]);
        float z = __half2float(g_Zh[idx]);
        float o = __half2float(g_Oh[idx]);
        h = fmaf(f, h - z, z);
        __stcs(out + idx, h * o);   // streaming store: don't evict hot gates
    }
}

// ---------------------------------------------------------------------------
extern "C" void kernel_launch(void* const* d_in, const int* in_sizes, int n_in,
                              void* d_out, int out_size)
{
    const float* x    = (const float*)d_in[0];  // [8,2048,512]
    const float* kern = (const float*)d_in[1];  // [2,512,1536]
    const float* bias = (const float*)d_in[2];  // [1536]
    const float* init = (const float*)d_in[3];  // [1,512]
    float* out = (float*)d_out;                 // [8,2048,512]

    cudaFuncSetAttribute(mma_gates, cudaFuncAttributeMaxDynamicSharedMemorySize, SMEM_REQ);

    prep_all<<<NXBLK + NWBLK, 256>>>(x, kern);
    mma_gates<<<dim3(NG / BN, MM / BM), 256, SMEM_REQ>>>(bias);
    scan_pass1<<<(B_ * NCH * U_) / 256, 256>>>();
    scan_pass23<<<(B_ * NCH * U_) / 256, 256>>>(init, out);
}